// round 11
// baseline (speedup 1.0000x reference)
#include <cuda_runtime.h>
#include <cuda_bf16.h>
#include <cuda_fp16.h>
#include <cstdint>

#define N_NODES 100000
#define N_EDGES 1000000
#define F_IN    128
#define H_OUT   64
#define BN_EPS  1e-3f

// ---------------- device scratch ----------------
__device__ __half2 g_h2[(size_t)N_NODES * 32];   // isd*BN-scaled hidden feats (fp16)
__device__ int   g_deg[N_NODES];
__device__ float g_isd[N_NODES];
__device__ int   g_rowstart[N_NODES];
__device__ int   g_cursor[N_NODES];
__device__ int   g_edst[N_EDGES];
__device__ int   g_total;
__device__ float g_sc[H_OUT];   // gamma*rsqrt(var+eps)
__device__ float g_tc[H_OUT];   // beta - mean*s

__device__ __forceinline__ uint32_t smem_u32(const void* p) {
    uint32_t a;
    asm("{ .reg .u64 t; cvta.to.shared.u64 t, %1; cvt.u32.u64 %0, t; }" : "=r"(a) : "l"(p));
    return a;
}

// ---------------- prep kernels ----------------
__global__ void zero_deg_kernel() {
    int i = blockIdx.x * blockDim.x + threadIdx.x;
    if (i < N_NODES) g_deg[i] = 0;
    if (i == 0) g_total = 0;
}

// 4 edges per thread, independent REDs (E divisible by 4)
__global__ void count_deg_kernel(const int4* __restrict__ ei2) {
    int t = blockIdx.x * blockDim.x + threadIdx.x;
    if (t < N_EDGES / 4) {
        int4 a = __ldg(&ei2[t * 2]);
        int4 b = __ldg(&ei2[t * 2 + 1]);
        atomicAdd(&g_deg[a.x], 1);
        atomicAdd(&g_deg[a.z], 1);
        atomicAdd(&g_deg[b.x], 1);
        atomicAdd(&g_deg[b.z], 1);
    }
}

// fused scan: warp inclusive scan + warp-aggregated atomic base.
__global__ void scan_fused_kernel(
    const float* __restrict__ gamma, const float* __restrict__ beta,
    const float* __restrict__ mean,  const float* __restrict__ var) {
    int i = blockIdx.x * blockDim.x + threadIdx.x;
    int lane = threadIdx.x & 31;
    if (blockIdx.x == 0 && threadIdx.x < H_OUT) {
        float s = gamma[threadIdx.x] * rsqrtf(var[threadIdx.x] + BN_EPS);
        g_sc[threadIdx.x] = s;
        g_tc[threadIdx.x] = beta[threadIdx.x] - mean[threadIdx.x] * s;
    }
    int d = (i < N_NODES) ? g_deg[i] : 0;
    int p = d;
    #pragma unroll
    for (int o = 1; o < 32; o <<= 1) {
        int u = __shfl_up_sync(0xffffffffu, p, o);
        if (lane >= o) p += u;
    }
    int base = 0;
    if (lane == 31) base = atomicAdd(&g_total, p);
    base = __shfl_sync(0xffffffffu, base, 31);
    if (i < N_NODES) {
        int row = base + p - d;
        g_rowstart[i] = row;
        g_cursor[i]   = row;
        float dd = (float)d;
        g_isd[i] = (dd > 0.f) ? rsqrtf(dd) : 0.f;
    }
}

// 4 edges per thread, 4 independent atomic->store chains
__global__ void scatter_kernel(const int4* __restrict__ ei2) {
    int t = blockIdx.x * blockDim.x + threadIdx.x;
    if (t < N_EDGES / 4) {
        int4 a = __ldg(&ei2[t * 2]);
        int4 b = __ldg(&ei2[t * 2 + 1]);
        int p0 = atomicAdd(&g_cursor[a.x], 1);
        int p1 = atomicAdd(&g_cursor[a.z], 1);
        int p2 = atomicAdd(&g_cursor[b.x], 1);
        int p3 = atomicAdd(&g_cursor[b.z], 1);
        g_edst[p0] = a.y;
        g_edst[p1] = a.w;
        g_edst[p2] = b.y;
        g_edst[p3] = b.w;
    }
}

// ---------------- tensor-core GEMM via mma.sync (bf16 3-split) ----------------
#define APITCH 272
#define SM_BS   0
#define SM_S    256
#define SM_A_HI 1024
#define SM_A_LO (SM_A_HI + 128 * APITCH)
#define SM_B_HI (SM_A_LO + 128 * APITCH)
#define SM_B_LO (SM_B_HI + 64 * APITCH)
#define GEMM_SMEM (SM_B_LO + 64 * APITCH)  // 105472 B

__device__ __forceinline__ void ldmx4(uint32_t* r, uint32_t a) {
    asm volatile("ldmatrix.sync.aligned.m8n8.x4.shared.b16 {%0,%1,%2,%3}, [%4];"
                 : "=r"(r[0]), "=r"(r[1]), "=r"(r[2]), "=r"(r[3]) : "r"(a));
}
__device__ __forceinline__ void ldmx2(uint32_t* r, uint32_t a) {
    asm volatile("ldmatrix.sync.aligned.m8n8.x2.shared.b16 {%0,%1}, [%2];"
                 : "=r"(r[0]), "=r"(r[1]) : "r"(a));
}
__device__ __forceinline__ void mma_bf16(float* c, const uint32_t* a, const uint32_t* b) {
    asm volatile(
        "mma.sync.aligned.m16n8k16.row.col.f32.bf16.bf16.f32 "
        "{%0,%1,%2,%3}, {%4,%5,%6,%7}, {%8,%9}, {%0,%1,%2,%3};"
        : "+f"(c[0]), "+f"(c[1]), "+f"(c[2]), "+f"(c[3])
        : "r"(a[0]), "r"(a[1]), "r"(a[2]), "r"(a[3]), "r"(b[0]), "r"(b[1]));
}
__device__ __forceinline__ uint32_t pack_bf16(float x, float y) {
    __nv_bfloat16 bx = __float2bfloat16(x), by = __float2bfloat16(y);
    return ((uint32_t)*(uint16_t*)&by << 16) | *(uint16_t*)&bx;
}

__global__ void __launch_bounds__(256) gemm_mma_kernel(
    const float* __restrict__ X, const float* __restrict__ W,
    const float* __restrict__ bias,
    const float* __restrict__ gamma, const float* __restrict__ var)
{
    extern __shared__ char smem[];
    uint32_t sb = smem_u32(smem);
    int tid = threadIdx.x, wid = tid >> 5, lane = tid & 31;
    int node0 = blockIdx.x * 128;

    float* bs = (float*)(smem + SM_BS);
    float* sv = (float*)(smem + SM_S);
    if (tid < 64) {
        float s = gamma[tid] * rsqrtf(var[tid] + BN_EPS);
        sv[tid] = s;
        bs[tid] = bias[tid] * s;
    }
    __syncthreads();

    {
        const float4* Xt = (const float4*)(X + (size_t)node0 * F_IN);
        #pragma unroll 4
        for (int i = tid; i < 4096; i += 256) {
            int r = i >> 5, c4 = i & 31;
            float4 v = make_float4(0.f, 0.f, 0.f, 0.f);
            if (node0 + r < N_NODES) v = Xt[i];
            float hx = __bfloat162float(__float2bfloat16(v.x));
            float hy = __bfloat162float(__float2bfloat16(v.y));
            float hz = __bfloat162float(__float2bfloat16(v.z));
            float hw = __bfloat162float(__float2bfloat16(v.w));
            uint2 hp, lp;
            hp.x = pack_bf16(v.x, v.y);
            hp.y = pack_bf16(v.z, v.w);
            lp.x = pack_bf16(v.x - hx, v.y - hy);
            lp.y = pack_bf16(v.z - hz, v.w - hw);
            uint32_t off = (uint32_t)(r * APITCH + c4 * 8);
            *(uint2*)(smem + SM_A_HI + off) = hp;
            *(uint2*)(smem + SM_A_LO + off) = lp;
        }
    }
    #pragma unroll 4
    for (int i = tid; i < F_IN * H_OUT; i += 256) {
        int k = i >> 6, n = i & 63;
        float w = W[i] * sv[n];
        float hi = __bfloat162float(__float2bfloat16(w));
        uint32_t off = (uint32_t)(n * APITCH + k * 2);
        *(__nv_bfloat16*)(smem + SM_B_HI + off) = __float2bfloat16(w);
        *(__nv_bfloat16*)(smem + SM_B_LO + off) = __float2bfloat16(w - hi);
    }
    __syncthreads();

    int warp_m = wid & 3;
    int warp_n = wid >> 2;

    uint32_t aAddr = sb + SM_A_HI
                   + (uint32_t)((warp_m * 32 + (lane & 15)) * APITCH)
                   + (uint32_t)((lane >> 4) * 16);
    uint32_t bAddr = sb + SM_B_HI
                   + (uint32_t)((warp_n * 32 + (lane & 7)) * APITCH)
                   + (uint32_t)(((lane >> 3) & 1) * 16);

    float c[2][4][4];
    #pragma unroll
    for (int mt = 0; mt < 2; mt++)
        #pragma unroll
        for (int nt = 0; nt < 4; nt++)
            #pragma unroll
            for (int q = 0; q < 4; q++) c[mt][nt][q] = 0.f;

    #pragma unroll
    for (int ks = 0; ks < 8; ks++) {
        uint32_t ko = (uint32_t)(ks * 32);
        uint32_t ah[2][4], al[2][4], bh[4][2], bl[4][2];
        #pragma unroll
        for (int mt = 0; mt < 2; mt++) {
            uint32_t a = aAddr + (uint32_t)(mt * 16 * APITCH) + ko;
            ldmx4(ah[mt], a);
            ldmx4(al[mt], a + (SM_A_LO - SM_A_HI));
        }
        #pragma unroll
        for (int nt = 0; nt < 4; nt++) {
            uint32_t b = bAddr + (uint32_t)(nt * 8 * APITCH) + ko;
            ldmx2(bh[nt], b);
            ldmx2(bl[nt], b + (SM_B_LO - SM_B_HI));
        }
        #pragma unroll
        for (int mt = 0; mt < 2; mt++)
            #pragma unroll
            for (int nt = 0; nt < 4; nt++) {
                mma_bf16(c[mt][nt], ah[mt], bh[nt]);
                mma_bf16(c[mt][nt], ah[mt], bl[nt]);
                mma_bf16(c[mt][nt], al[mt], bh[nt]);
            }
    }

    int rbase = node0 + warp_m * 32 + (lane >> 2);
    int cgrp  = (lane & 3) * 2;
    #pragma unroll
    for (int mt = 0; mt < 2; mt++) {
        int n1 = rbase + mt * 16;
        int n2 = n1 + 8;
        float i1 = (n1 < N_NODES) ? __ldg(&g_isd[n1]) : 0.f;
        float i2 = (n2 < N_NODES) ? __ldg(&g_isd[n2]) : 0.f;
        #pragma unroll
        for (int nt = 0; nt < 4; nt++) {
            int col = warp_n * 32 + nt * 8 + cgrp;
            float2 bv = *(float2*)&bs[col];
            if (n1 < N_NODES)
                g_h2[(size_t)n1 * 32 + (col >> 1)] =
                    __floats2half2_rn((c[mt][nt][0] + bv.x) * i1, (c[mt][nt][1] + bv.y) * i1);
            if (n2 < N_NODES)
                g_h2[(size_t)n2 * 32 + (col >> 1)] =
                    __floats2half2_rn((c[mt][nt][2] + bv.x) * i2, (c[mt][nt][3] + bv.y) * i2);
        }
    }
}

// ---------------- fused gather: warp per node, 4 neighbors per step ----------------
// Lane = sub*8 + r: subgroup sub (0..3) handles neighbor j+sub / j+4+sub,
// lane loads uint4 (8 halves = cols r*8..r*8+7) of that neighbor's row.
// out[i] = t + 0.5*deg^1.5*h2[i] + 0.5*isd[i]*sum_d h2[d]
__global__ __launch_bounds__(256) void gather_kernel(float* __restrict__ out)
{
    int w    = (blockIdx.x * blockDim.x + threadIdx.x) >> 5;
    int lane = threadIdx.x & 31;
    if (w >= N_NODES) return;

    int sub = lane >> 3, r = lane & 7;
    int start = g_rowstart[w];
    int deg   = g_deg[w];
    int end   = start + deg;

    const uint4* H4 = (const uint4*)g_h2;   // 8 uint4 per node row

    float2 acc0 = make_float2(0.f, 0.f), acc1 = make_float2(0.f, 0.f);
    float2 acc2 = make_float2(0.f, 0.f), acc3 = make_float2(0.f, 0.f);

    for (int base = start; base < end; base += 32) {
        int cnt = min(32, end - base);
        int id = (lane < cnt) ? g_edst[base + lane] : 0;
        for (int j = 0; j < cnt; j += 8) {
            int j0 = j + sub, j1 = j + 4 + sub;
            bool v0 = j0 < cnt, v1 = j1 < cnt;
            int d0 = __shfl_sync(0xffffffffu, id, j0 & 31);
            int d1 = __shfl_sync(0xffffffffu, id, j1 & 31);
            uint4 u0, u1;
            if (v0) u0 = __ldg(&H4[(size_t)d0 * 8 + r]);
            if (v1) u1 = __ldg(&H4[(size_t)d1 * 8 + r]);
            if (v0) {
                const __half2* ph = (const __half2*)&u0;
                float2 f0 = __half22float2(ph[0]), f1 = __half22float2(ph[1]);
                float2 f2 = __half22float2(ph[2]), f3 = __half22float2(ph[3]);
                acc0.x += f0.x; acc0.y += f0.y; acc1.x += f1.x; acc1.y += f1.y;
                acc2.x += f2.x; acc2.y += f2.y; acc3.x += f3.x; acc3.y += f3.y;
            }
            if (v1) {
                const __half2* ph = (const __half2*)&u1;
                float2 f0 = __half22float2(ph[0]), f1 = __half22float2(ph[1]);
                float2 f2 = __half22float2(ph[2]), f3 = __half22float2(ph[3]);
                acc0.x += f0.x; acc0.y += f0.y; acc1.x += f1.x; acc1.y += f1.y;
                acc2.x += f2.x; acc2.y += f2.y; acc3.x += f3.x; acc3.y += f3.y;
            }
        }
    }

    // reduce across the 4 subgroups (lanes same r, differing bits 3..4)
    #pragma unroll
    for (int off = 8; off <= 16; off <<= 1) {
        acc0.x += __shfl_xor_sync(0xffffffffu, acc0.x, off);
        acc0.y += __shfl_xor_sync(0xffffffffu, acc0.y, off);
        acc1.x += __shfl_xor_sync(0xffffffffu, acc1.x, off);
        acc1.y += __shfl_xor_sync(0xffffffffu, acc1.y, off);
        acc2.x += __shfl_xor_sync(0xffffffffu, acc2.x, off);
        acc2.y += __shfl_xor_sync(0xffffffffu, acc2.y, off);
        acc3.x += __shfl_xor_sync(0xffffffffu, acc3.x, off);
        acc3.y += __shfl_xor_sync(0xffffffffu, acc3.y, off);
    }

    // lane writes cols c = r*8 + sub*2, c+1 ; pick matching accumulator
    float2 accsel = (sub == 0) ? acc0 : (sub == 1) ? acc1 : (sub == 2) ? acc2 : acc3;

    float dd    = (float)deg;
    float isdi  = g_isd[w];
    float selfc = 0.5f * dd * sqrtf(dd);     // deg >= 1 always

    int c = r * 8 + sub * 2;
    float2 tt = *(const float2*)&g_tc[c];
    float2 hv = __half22float2(g_h2[(size_t)w * 32 + (c >> 1)]);
    float2 o;
    o.x = tt.x + selfc * hv.x + 0.5f * isdi * accsel.x;
    o.y = tt.y + selfc * hv.y + 0.5f * isdi * accsel.y;
    *(float2*)&out[(size_t)w * H_OUT + c] = o;
}

// ---------------- launch ----------------
extern "C" void kernel_launch(void* const* d_in, const int* in_sizes, int n_in,
                              void* d_out, int out_size) {
    const float* X     = (const float*)d_in[0];
    const float* W     = (const float*)d_in[1];
    const float* bias  = (const float*)d_in[2];
    const float* gamma = (const float*)d_in[3];
    const float* beta  = (const float*)d_in[4];
    const float* mean  = (const float*)d_in[5];
    const float* var   = (const float*)d_in[6];
    const int4*  ei2   = (const int4*)d_in[7];
    float* out = (float*)d_out;

    zero_deg_kernel<<<(N_NODES + 255) / 256, 256>>>();
    count_deg_kernel<<<(N_EDGES / 4 + 255) / 256, 256>>>(ei2);
    scan_fused_kernel<<<(N_NODES + 255) / 256, 256>>>(gamma, beta, mean, var);
    scatter_kernel<<<(N_EDGES / 4 + 255) / 256, 256>>>(ei2);

    cudaFuncSetAttribute(gemm_mma_kernel, cudaFuncAttributeMaxDynamicSharedMemorySize, GEMM_SMEM);
    gemm_mma_kernel<<<(N_NODES + 127) / 128, 256, GEMM_SMEM>>>(X, W, bias, gamma, var);

    gather_kernel<<<(N_NODES * 32 + 255) / 256, 256>>>(out);
}

// round 12
// speedup vs baseline: 1.2064x; 1.2064x over previous
#include <cuda_runtime.h>
#include <cuda_bf16.h>
#include <cuda_fp16.h>
#include <cstdint>

#define N_NODES 100000
#define N_EDGES 1000000
#define F_IN    128
#define H_OUT   64
#define BN_EPS  1e-3f

// ---------------- device scratch ----------------
__device__ __half2 g_h2[(size_t)N_NODES * 32];   // isd*BN-scaled hidden feats (fp16)
__device__ int   g_deg[N_NODES];
__device__ float g_isd[N_NODES];
__device__ int   g_rowstart[N_NODES];
__device__ int   g_cursor[N_NODES];
__device__ int   g_edst[N_EDGES];
__device__ int   g_total;
__device__ float g_sc[H_OUT];
__device__ float g_tc[H_OUT];   // beta - mean*s

__device__ __forceinline__ uint32_t smem_u32(const void* p) {
    uint32_t a;
    asm("{ .reg .u64 t; cvta.to.shared.u64 t, %1; cvt.u32.u64 %0, t; }" : "=r"(a) : "l"(p));
    return a;
}

// ---------------- prep kernels (scalar forms — R10 best config) ----------------
__global__ void zero_deg_kernel() {
    int i = blockIdx.x * blockDim.x + threadIdx.x;
    if (i < N_NODES) g_deg[i] = 0;
    if (i == 0) g_total = 0;
}
__global__ void count_deg_kernel(const int2* __restrict__ ei) {
    int e = blockIdx.x * blockDim.x + threadIdx.x;
    if (e < N_EDGES) atomicAdd(&g_deg[ei[e].x], 1);
}
__global__ void scan_fused_kernel(
    const float* __restrict__ gamma, const float* __restrict__ beta,
    const float* __restrict__ mean,  const float* __restrict__ var) {
    int i = blockIdx.x * blockDim.x + threadIdx.x;
    int lane = threadIdx.x & 31;
    if (blockIdx.x == 0 && threadIdx.x < H_OUT) {
        float s = gamma[threadIdx.x] * rsqrtf(var[threadIdx.x] + BN_EPS);
        g_sc[threadIdx.x] = s;
        g_tc[threadIdx.x] = beta[threadIdx.x] - mean[threadIdx.x] * s;
    }
    int d = (i < N_NODES) ? g_deg[i] : 0;
    int p = d;
    #pragma unroll
    for (int o = 1; o < 32; o <<= 1) {
        int u = __shfl_up_sync(0xffffffffu, p, o);
        if (lane >= o) p += u;
    }
    int base = 0;
    if (lane == 31) base = atomicAdd(&g_total, p);
    base = __shfl_sync(0xffffffffu, base, 31);
    if (i < N_NODES) {
        int row = base + p - d;
        g_rowstart[i] = row;
        g_cursor[i]   = row;
        float dd = (float)d;
        g_isd[i] = (dd > 0.f) ? rsqrtf(dd) : 0.f;
    }
}
__global__ void scatter_kernel(const int2* __restrict__ ei) {
    int e = blockIdx.x * blockDim.x + threadIdx.x;
    if (e < N_EDGES) {
        int2 p = __ldg(&ei[e]);
        int pos = atomicAdd(&g_cursor[p.x], 1);
        g_edst[pos] = p.y;
    }
}

// ---------------- tensor-core GEMM via mma.sync (bf16 3-split) ----------------
#define APITCH 272
#define SM_BS   0
#define SM_S    256
#define SM_A_HI 1024
#define SM_A_LO (SM_A_HI + 128 * APITCH)
#define SM_B_HI (SM_A_LO + 128 * APITCH)
#define SM_B_LO (SM_B_HI + 64 * APITCH)
#define GEMM_SMEM (SM_B_LO + 64 * APITCH)  // 105472 B

__device__ __forceinline__ void ldmx4(uint32_t* r, uint32_t a) {
    asm volatile("ldmatrix.sync.aligned.m8n8.x4.shared.b16 {%0,%1,%2,%3}, [%4];"
                 : "=r"(r[0]), "=r"(r[1]), "=r"(r[2]), "=r"(r[3]) : "r"(a));
}
__device__ __forceinline__ void ldmx2(uint32_t* r, uint32_t a) {
    asm volatile("ldmatrix.sync.aligned.m8n8.x2.shared.b16 {%0,%1}, [%2];"
                 : "=r"(r[0]), "=r"(r[1]) : "r"(a));
}
__device__ __forceinline__ void mma_bf16(float* c, const uint32_t* a, const uint32_t* b) {
    asm volatile(
        "mma.sync.aligned.m16n8k16.row.col.f32.bf16.bf16.f32 "
        "{%0,%1,%2,%3}, {%4,%5,%6,%7}, {%8,%9}, {%0,%1,%2,%3};"
        : "+f"(c[0]), "+f"(c[1]), "+f"(c[2]), "+f"(c[3])
        : "r"(a[0]), "r"(a[1]), "r"(a[2]), "r"(a[3]), "r"(b[0]), "r"(b[1]));
}
__device__ __forceinline__ uint32_t pack_bf16(float x, float y) {
    __nv_bfloat16 bx = __float2bfloat16(x), by = __float2bfloat16(y);
    return ((uint32_t)*(uint16_t*)&by << 16) | *(uint16_t*)&bx;
}

__global__ void __launch_bounds__(256) gemm_mma_kernel(
    const float* __restrict__ X, const float* __restrict__ W,
    const float* __restrict__ bias,
    const float* __restrict__ gamma, const float* __restrict__ var)
{
    extern __shared__ char smem[];
    uint32_t sb = smem_u32(smem);
    int tid = threadIdx.x, wid = tid >> 5, lane = tid & 31;
    int node0 = blockIdx.x * 128;

    float* bs = (float*)(smem + SM_BS);
    float* sv = (float*)(smem + SM_S);
    if (tid < 64) {
        float s = gamma[tid] * rsqrtf(var[tid] + BN_EPS);
        sv[tid] = s;
        bs[tid] = bias[tid] * s;
    }
    __syncthreads();

    {
        const float4* Xt = (const float4*)(X + (size_t)node0 * F_IN);
        #pragma unroll 4
        for (int i = tid; i < 4096; i += 256) {
            int r = i >> 5, c4 = i & 31;
            float4 v = make_float4(0.f, 0.f, 0.f, 0.f);
            if (node0 + r < N_NODES) v = Xt[i];
            float hx = __bfloat162float(__float2bfloat16(v.x));
            float hy = __bfloat162float(__float2bfloat16(v.y));
            float hz = __bfloat162float(__float2bfloat16(v.z));
            float hw = __bfloat162float(__float2bfloat16(v.w));
            uint2 hp, lp;
            hp.x = pack_bf16(v.x, v.y);
            hp.y = pack_bf16(v.z, v.w);
            lp.x = pack_bf16(v.x - hx, v.y - hy);
            lp.y = pack_bf16(v.z - hz, v.w - hw);
            uint32_t off = (uint32_t)(r * APITCH + c4 * 8);
            *(uint2*)(smem + SM_A_HI + off) = hp;
            *(uint2*)(smem + SM_A_LO + off) = lp;
        }
    }
    #pragma unroll 4
    for (int i = tid; i < F_IN * H_OUT; i += 256) {
        int k = i >> 6, n = i & 63;
        float w = W[i] * sv[n];
        float hi = __bfloat162float(__float2bfloat16(w));
        uint32_t off = (uint32_t)(n * APITCH + k * 2);
        *(__nv_bfloat16*)(smem + SM_B_HI + off) = __float2bfloat16(w);
        *(__nv_bfloat16*)(smem + SM_B_LO + off) = __float2bfloat16(w - hi);
    }
    __syncthreads();

    int warp_m = wid & 3;
    int warp_n = wid >> 2;

    uint32_t aAddr = sb + SM_A_HI
                   + (uint32_t)((warp_m * 32 + (lane & 15)) * APITCH)
                   + (uint32_t)((lane >> 4) * 16);
    uint32_t bAddr = sb + SM_B_HI
                   + (uint32_t)((warp_n * 32 + (lane & 7)) * APITCH)
                   + (uint32_t)(((lane >> 3) & 1) * 16);

    float c[2][4][4];
    #pragma unroll
    for (int mt = 0; mt < 2; mt++)
        #pragma unroll
        for (int nt = 0; nt < 4; nt++)
            #pragma unroll
            for (int q = 0; q < 4; q++) c[mt][nt][q] = 0.f;

    #pragma unroll
    for (int ks = 0; ks < 8; ks++) {
        uint32_t ko = (uint32_t)(ks * 32);
        uint32_t ah[2][4], al[2][4], bh[4][2], bl[4][2];
        #pragma unroll
        for (int mt = 0; mt < 2; mt++) {
            uint32_t a = aAddr + (uint32_t)(mt * 16 * APITCH) + ko;
            ldmx4(ah[mt], a);
            ldmx4(al[mt], a + (SM_A_LO - SM_A_HI));
        }
        #pragma unroll
        for (int nt = 0; nt < 4; nt++) {
            uint32_t b = bAddr + (uint32_t)(nt * 8 * APITCH) + ko;
            ldmx2(bh[nt], b);
            ldmx2(bl[nt], b + (SM_B_LO - SM_B_HI));
        }
        #pragma unroll
        for (int mt = 0; mt < 2; mt++)
            #pragma unroll
            for (int nt = 0; nt < 4; nt++) {
                mma_bf16(c[mt][nt], ah[mt], bh[nt]);
                mma_bf16(c[mt][nt], ah[mt], bl[nt]);
                mma_bf16(c[mt][nt], al[mt], bh[nt]);
            }
    }

    int rbase = node0 + warp_m * 32 + (lane >> 2);
    int cgrp  = (lane & 3) * 2;
    #pragma unroll
    for (int mt = 0; mt < 2; mt++) {
        int n1 = rbase + mt * 16;
        int n2 = n1 + 8;
        float i1 = (n1 < N_NODES) ? __ldg(&g_isd[n1]) : 0.f;
        float i2 = (n2 < N_NODES) ? __ldg(&g_isd[n2]) : 0.f;
        #pragma unroll
        for (int nt = 0; nt < 4; nt++) {
            int col = warp_n * 32 + nt * 8 + cgrp;
            float2 bv = *(float2*)&bs[col];
            if (n1 < N_NODES)
                g_h2[(size_t)n1 * 32 + (col >> 1)] =
                    __floats2half2_rn((c[mt][nt][0] + bv.x) * i1, (c[mt][nt][1] + bv.y) * i1);
            if (n2 < N_NODES)
                g_h2[(size_t)n2 * 32 + (col >> 1)] =
                    __floats2half2_rn((c[mt][nt][2] + bv.x) * i2, (c[mt][nt][3] + bv.y) * i2);
        }
    }
}

// ---------------- gather v3: 8-lane group per node, fp16 pair-tree ----------------
// Lane r of a group owns cols r*8..r*8+7 (one uint4 = 4 half2 per neighbor row).
// 4 neighbors summed in half2 (3 HADD2) before one f32 accumulate.
// out[i] = t + 0.5*deg^1.5*h2[i] + 0.5*isd[i]*sum_d h2[d]
__global__ __launch_bounds__(256) void gather_kernel(float* __restrict__ out)
{
    int node = (blockIdx.x * blockDim.x + threadIdx.x) >> 3;
    if (node >= N_NODES) return;
    int lane = threadIdx.x & 31;
    int r    = lane & 7;
    int gb   = lane & 24;                 // group base lane (0,8,16,24)
    unsigned gmask = 0xFFu << gb;

    int start = g_rowstart[node];
    int deg   = g_deg[node];
    int end   = start + deg;

    const uint4* H4 = (const uint4*)g_h2;   // 8 uint4 per node row

    float2 acc[4];
    #pragma unroll
    for (int q = 0; q < 4; q++) acc[q] = make_float2(0.f, 0.f);

    for (int base = start; base < end; base += 8) {
        int cnt = min(8, end - base);
        int id = (r < cnt) ? __ldg(&g_edst[base + r]) : 0;
        int j = 0;
        for (; j + 4 <= cnt; j += 4) {
            int d0 = __shfl_sync(gmask, id, gb + j);
            int d1 = __shfl_sync(gmask, id, gb + j + 1);
            int d2 = __shfl_sync(gmask, id, gb + j + 2);
            int d3 = __shfl_sync(gmask, id, gb + j + 3);
            uint4 u0 = __ldg(&H4[(size_t)d0 * 8 + r]);
            uint4 u1 = __ldg(&H4[(size_t)d1 * 8 + r]);
            uint4 u2 = __ldg(&H4[(size_t)d2 * 8 + r]);
            uint4 u3 = __ldg(&H4[(size_t)d3 * 8 + r]);
            const __half2* p0 = (const __half2*)&u0;
            const __half2* p1 = (const __half2*)&u1;
            const __half2* p2 = (const __half2*)&u2;
            const __half2* p3 = (const __half2*)&u3;
            #pragma unroll
            for (int q = 0; q < 4; q++) {
                __half2 s = __hadd2(__hadd2(p0[q], p1[q]), __hadd2(p2[q], p3[q]));
                float2 f = __half22float2(s);
                acc[q].x += f.x;
                acc[q].y += f.y;
            }
        }
        for (; j < cnt; j++) {
            int d0 = __shfl_sync(gmask, id, gb + j);
            uint4 u0 = __ldg(&H4[(size_t)d0 * 8 + r]);
            const __half2* p0 = (const __half2*)&u0;
            #pragma unroll
            for (int q = 0; q < 4; q++) {
                float2 f = __half22float2(p0[q]);
                acc[q].x += f.x;
                acc[q].y += f.y;
            }
        }
    }

    float dd    = (float)deg;
    float isdi  = g_isd[node];
    float selfc = 0.5f * dd * sqrtf(dd);   // deg >= 1 always
    float hisd  = 0.5f * isdi;

    int c0 = r * 8;
    uint4 hu = H4[(size_t)node * 8 + r];
    const __half2* ph = (const __half2*)&hu;
    float o[8];
    #pragma unroll
    for (int q = 0; q < 4; q++) {
        float2 hv = __half22float2(ph[q]);
        float2 tt = *(const float2*)&g_tc[c0 + q * 2];
        o[q * 2]     = tt.x + selfc * hv.x + hisd * acc[q].x;
        o[q * 2 + 1] = tt.y + selfc * hv.y + hisd * acc[q].y;
    }
    float4* dst = (float4*)&out[(size_t)node * H_OUT + c0];
    dst[0] = make_float4(o[0], o[1], o[2], o[3]);
    dst[1] = make_float4(o[4], o[5], o[6], o[7]);
}

// ---------------- launch ----------------
extern "C" void kernel_launch(void* const* d_in, const int* in_sizes, int n_in,
                              void* d_out, int out_size) {
    const float* X     = (const float*)d_in[0];
    const float* W     = (const float*)d_in[1];
    const float* bias  = (const float*)d_in[2];
    const float* gamma = (const float*)d_in[3];
    const float* beta  = (const float*)d_in[4];
    const float* mean  = (const float*)d_in[5];
    const float* var   = (const float*)d_in[6];
    const int2*  ei    = (const int2*)d_in[7];
    float* out = (float*)d_out;

    zero_deg_kernel<<<(N_NODES + 255) / 256, 256>>>();
    count_deg_kernel<<<(N_EDGES + 255) / 256, 256>>>(ei);
    scan_fused_kernel<<<(N_NODES + 255) / 256, 256>>>(gamma, beta, mean, var);
    scatter_kernel<<<(N_EDGES + 255) / 256, 256>>>(ei);

    cudaFuncSetAttribute(gemm_mma_kernel, cudaFuncAttributeMaxDynamicSharedMemorySize, GEMM_SMEM);
    gemm_mma_kernel<<<(N_NODES + 127) / 128, 256, GEMM_SMEM>>>(X, W, bias, gamma, var);

    gather_kernel<<<(N_NODES * 8 + 255) / 256, 256>>>(out);
}